// round 2
// baseline (speedup 1.0000x reference)
#include <cuda_runtime.h>

// Problem constants (fixed shapes from the reference setup)
#define NB   16      // batch
#define NT   128     // time
#define NHWC 25088   // 56*56*8 floats per frame
#define NS4  6272    // NHWC / 4 (float4 strips per frame)
#define NC   8       // channels
#define KCH  4       // time chunks
#define TC   (NT / KCH)             // 32 frames per chunk
#define NBLK_S ((NS4 + 255) / 256)  // 25 blocks over the spatial strip
#define NBLKS  (NB * KCH * NBLK_S)  // 1600 total blocks
#define NSLOT  20                   // floats per partial slot (17 used, padded)

// Scratch (no device allocation allowed -> __device__ globals).
// Every block writes its whole slot every launch => no init kernel needed.
__device__ float        g_part[NBLKS][NSLOT];
__device__ unsigned int g_ctr;   // zero-inited at load; last block resets to 0

__global__ __launch_bounds__(256) void fused_kernel(const float4* __restrict__ x,
                                                    const int*   __restrict__ length,
                                                    const float* __restrict__ count,
                                                    float*       __restrict__ out) {
    const int s4    = blockIdx.x * 256 + threadIdx.x;
    const bool live = (s4 < NS4);
    const int b     = blockIdx.z;
    const int chunk = blockIdx.y;
    const int len   = __ldg(&length[b]);
    const int t0    = chunk * TC;
    const float4* base = x + (size_t)b * NT * NS4 + (live ? s4 : 0);

    float ax = 0.f, ay = 0.f, az = 0.f, aw = 0.f;   // active sums (4 channels)
    float tx = 0.f, ty = 0.f, tz = 0.f, tw = 0.f;   // total sums
    float ttv = 0.f;
    float px = 0.f, py = 0.f, pz = 0.f, pw = 0.f;   // previous masked frame

    if (live) {
        if (t0 > 0 && (t0 - 1) < len) {
            float4 p = base[(size_t)(t0 - 1) * NS4];
            px = p.x; py = p.y; pz = p.z; pw = p.w;
        }
        #pragma unroll 4
        for (int t = t0; t < t0 + TC; ++t) {
            float4 v = base[(size_t)t * NS4];
            tx += v.x; ty += v.y; tz += v.z; tw += v.w;
            float cx, cy, cz, cw;
            if (t < len) {
                cx = v.x; cy = v.y; cz = v.z; cw = v.w;
                ax += v.x; ay += v.y; az += v.z; aw += v.w;
            } else {
                cx = 0.f; cy = 0.f; cz = 0.f; cw = 0.f;
            }
            if (t > 0) {   // skip only the global t=0 (chunk 0, first iter)
                ttv += fabsf(cx - px) + fabsf(cy - py) + fabsf(cz - pz) + fabsf(cw - pw);
            }
            px = cx; py = cy; pz = cz; pw = cw;
        }
    }

    // --- block reduction ---
    #pragma unroll
    for (int m = 16; m >= 1; m >>= 1)
        ttv += __shfl_xor_sync(0xffffffffu, ttv, m);
    // Parity-preserving reduce: even lanes hold channels 0-3, odd lanes 4-7
    #pragma unroll
    for (int m = 2; m <= 16; m <<= 1) {
        ax += __shfl_xor_sync(0xffffffffu, ax, m);
        ay += __shfl_xor_sync(0xffffffffu, ay, m);
        az += __shfl_xor_sync(0xffffffffu, az, m);
        aw += __shfl_xor_sync(0xffffffffu, aw, m);
        tx += __shfl_xor_sync(0xffffffffu, tx, m);
        ty += __shfl_xor_sync(0xffffffffu, ty, m);
        tz += __shfl_xor_sync(0xffffffffu, tz, m);
        tw += __shfl_xor_sync(0xffffffffu, tw, m);
    }

    __shared__ float sh_a[8][NC];
    __shared__ float sh_t[8][NC];
    __shared__ float sh_v[8];
    const int w = threadIdx.x >> 5, lane = threadIdx.x & 31;
    if (lane == 0) {
        sh_a[w][0] = ax; sh_a[w][1] = ay; sh_a[w][2] = az; sh_a[w][3] = aw;
        sh_t[w][0] = tx; sh_t[w][1] = ty; sh_t[w][2] = tz; sh_t[w][3] = tw;
        sh_v[w] = ttv;
    } else if (lane == 1) {
        sh_a[w][4] = ax; sh_a[w][5] = ay; sh_a[w][6] = az; sh_a[w][7] = aw;
        sh_t[w][4] = tx; sh_t[w][5] = ty; sh_t[w][6] = tz; sh_t[w][7] = tw;
    }
    __syncthreads();

    const int slot = (b * KCH + chunk) * NBLK_S + blockIdx.x;
    if (threadIdx.x < NC) {
        const int c = threadIdx.x;
        float sa = 0.f, st = 0.f;
        #pragma unroll
        for (int w2 = 0; w2 < 8; ++w2) { sa += sh_a[w2][c]; st += sh_t[w2][c]; }
        g_part[slot][c]      = sa;
        g_part[slot][NC + c] = st;
    } else if (threadIdx.x == NC) {
        float s = 0.f;
        #pragma unroll
        for (int w2 = 0; w2 < 8; ++w2) s += sh_v[w2];
        g_part[slot][16] = s;
    }

    // --- last-block-done final reduction (threadFenceReduction pattern) ---
    __threadfence();
    __shared__ bool s_last;
    if (threadIdx.x == 0) {
        unsigned int n = atomicAdd(&g_ctr, 1u);
        s_last = (n == NBLKS - 1);
    }
    __syncthreads();
    if (!s_last) return;
    if (threadIdx.x == 0) g_ctr = 0;   // keep graph replays deterministic

    __shared__ float sh_ttv[NB];
    __shared__ float sh_act[NB][NC];
    __shared__ float sh_tot[NB][NC];
    // 8 warps; each warp reduces 2 batches (100 slots each)
    #pragma unroll
    for (int k = 0; k < 2; ++k) {
        const int bb = w * 2 + k;
        float a[NC], t[NC];
        float v = 0.f;
        #pragma unroll
        for (int c = 0; c < NC; ++c) { a[c] = 0.f; t[c] = 0.f; }
        for (int j = lane; j < KCH * NBLK_S; j += 32) {
            const float* p = g_part[bb * KCH * NBLK_S + j];
            #pragma unroll
            for (int c = 0; c < NC; ++c) {
                a[c] += __ldcg(&p[c]);
                t[c] += __ldcg(&p[NC + c]);
            }
            v += __ldcg(&p[16]);
        }
        #pragma unroll
        for (int m = 16; m >= 1; m >>= 1) {
            #pragma unroll
            for (int c = 0; c < NC; ++c) {
                a[c] += __shfl_xor_sync(0xffffffffu, a[c], m);
                t[c] += __shfl_xor_sync(0xffffffffu, t[c], m);
            }
            v += __shfl_xor_sync(0xffffffffu, v, m);
        }
        if (lane == 0) {
            sh_ttv[bb] = v;
            #pragma unroll
            for (int c = 0; c < NC; ++c) { sh_act[bb][c] = a[c]; sh_tot[bb][c] = t[c]; }
        }
    }
    __syncthreads();

    if (threadIdx.x < NB) {
        const int bb = threadIdx.x;
        float tv = 0.f;
        #pragma unroll
        for (int i = 0; i < NB; ++i) tv += sh_ttv[i];
        float ah = 0.f, bh = 0.f;
        #pragma unroll
        for (int c = 0; c < NC; ++c) {
            const float a  = sh_act[bb][c];
            const float tt = sh_tot[bb][c];
            float e  = a - __ldg(&count[bb * NC + c]);
            float ae = fabsf(e);
            ah += (ae <= 1.f) ? 0.5f * e * e : (ae - 0.5f);
            float eb  = tt - a;
            float aeb = fabsf(eb);
            bh += (aeb <= 1.f) ? 0.5f * eb * eb : (aeb - 0.5f);
        }
        out[bb] = ah * (1.f / NC) + bh * (1.f / NC) + tv * 0.1f;
    }
}

extern "C" void kernel_launch(void* const* d_in, const int* in_sizes, int n_in,
                              void* d_out, int out_size) {
    const float* cam    = (const float*)d_in[0];
    const float* count  = (const float*)d_in[1];
    const int*   length = (const int*)d_in[2];
    float*       out    = (float*)d_out;

    dim3 grid(NBLK_S, KCH, NB);
    fused_kernel<<<grid, 256>>>((const float4*)cam, length, count, out);
}

// round 3
// speedup vs baseline: 1.1633x; 1.1633x over previous
#include <cuda_runtime.h>

// Problem constants (fixed shapes from the reference setup)
#define NB   16      // batch
#define NT   128     // time
#define NHWC 25088   // 56*56*8 floats per frame
#define NS4  6272    // NHWC / 4 (float4 strips per frame)
#define NC   8       // channels
#define KCH  4       // time chunks
#define TC   (NT / KCH)             // 32 frames per chunk
#define BT   224                    // block threads; NS4 = 28 * 224 exactly
#define NW   (BT / 32)              // 7 warps
#define NBLK_S (NS4 / BT)           // 28 blocks over the spatial strip
#define SLOTS_PER_B (KCH * NBLK_S)  // 112
#define NBLKS  (NB * SLOTS_PER_B)   // 1792 total blocks
#define NSLOT  20                   // floats per partial slot (17 used, padded)

// Scratch (no device allocation allowed -> __device__ globals).
// Every block writes its whole slot every launch => no init kernel needed.
__device__ float g_part[NBLKS][NSLOT];

__global__ __launch_bounds__(BT) void reduce_kernel(const float4* __restrict__ x,
                                                    const int* __restrict__ length) {
    const int s4    = blockIdx.x * BT + threadIdx.x;   // always < NS4
    const int b     = blockIdx.z;
    const int chunk = blockIdx.y;
    const int len   = __ldg(&length[b]);
    const int t0    = chunk * TC;
    const float4* base = x + (size_t)b * NT * NS4 + s4;

    float ax = 0.f, ay = 0.f, az = 0.f, aw = 0.f;   // active sums (4 channels)
    float tx = 0.f, ty = 0.f, tz = 0.f, tw = 0.f;   // total sums
    float ttv = 0.f;
    float px = 0.f, py = 0.f, pz = 0.f, pw = 0.f;   // previous masked frame

    if (t0 > 0 && (t0 - 1) < len) {
        float4 p = base[(size_t)(t0 - 1) * NS4];
        px = p.x; py = p.y; pz = p.z; pw = p.w;
    }
    #pragma unroll 8
    for (int t = t0; t < t0 + TC; ++t) {
        float4 v = base[(size_t)t * NS4];
        tx += v.x; ty += v.y; tz += v.z; tw += v.w;
        float cx, cy, cz, cw;
        if (t < len) {
            cx = v.x; cy = v.y; cz = v.z; cw = v.w;
            ax += v.x; ay += v.y; az += v.z; aw += v.w;
        } else {
            cx = 0.f; cy = 0.f; cz = 0.f; cw = 0.f;
        }
        if (t > 0) {   // skip only the global t=0 (chunk 0, first iter)
            ttv += fabsf(cx - px) + fabsf(cy - py) + fabsf(cz - pz) + fabsf(cw - pw);
        }
        px = cx; py = cy; pz = cz; pw = cw;
    }

    // --- block reduction ---
    #pragma unroll
    for (int m = 16; m >= 1; m >>= 1)
        ttv += __shfl_xor_sync(0xffffffffu, ttv, m);
    // Parity-preserving reduce: even lanes hold channels 0-3, odd lanes 4-7
    #pragma unroll
    for (int m = 2; m <= 16; m <<= 1) {
        ax += __shfl_xor_sync(0xffffffffu, ax, m);
        ay += __shfl_xor_sync(0xffffffffu, ay, m);
        az += __shfl_xor_sync(0xffffffffu, az, m);
        aw += __shfl_xor_sync(0xffffffffu, aw, m);
        tx += __shfl_xor_sync(0xffffffffu, tx, m);
        ty += __shfl_xor_sync(0xffffffffu, ty, m);
        tz += __shfl_xor_sync(0xffffffffu, tz, m);
        tw += __shfl_xor_sync(0xffffffffu, tw, m);
    }

    __shared__ float sh_a[NW][NC];
    __shared__ float sh_t[NW][NC];
    __shared__ float sh_v[NW];
    const int w = threadIdx.x >> 5, lane = threadIdx.x & 31;
    if (lane == 0) {
        sh_a[w][0] = ax; sh_a[w][1] = ay; sh_a[w][2] = az; sh_a[w][3] = aw;
        sh_t[w][0] = tx; sh_t[w][1] = ty; sh_t[w][2] = tz; sh_t[w][3] = tw;
        sh_v[w] = ttv;
    } else if (lane == 1) {
        sh_a[w][4] = ax; sh_a[w][5] = ay; sh_a[w][6] = az; sh_a[w][7] = aw;
        sh_t[w][4] = tx; sh_t[w][5] = ty; sh_t[w][6] = tz; sh_t[w][7] = tw;
    }
    __syncthreads();

    const int slot = (b * KCH + chunk) * NBLK_S + blockIdx.x;
    if (threadIdx.x < NC) {
        const int c = threadIdx.x;
        float sa = 0.f, st = 0.f;
        #pragma unroll
        for (int w2 = 0; w2 < NW; ++w2) { sa += sh_a[w2][c]; st += sh_t[w2][c]; }
        g_part[slot][c]      = sa;
        g_part[slot][NC + c] = st;
    } else if (threadIdx.x == NC) {
        float s = 0.f;
        #pragma unroll
        for (int w2 = 0; w2 < NW; ++w2) s += sh_v[w2];
        g_part[slot][16] = s;
    }
}

__global__ __launch_bounds__(512) void final_kernel(const float* __restrict__ count,
                                                    float* __restrict__ out) {
    __shared__ float sh_ttv[NB];
    __shared__ float sh_act[NB][NC];
    __shared__ float sh_tot[NB][NC];
    const int w = threadIdx.x >> 5, lane = threadIdx.x & 31;  // 16 warps, one per batch

    float a[NC], t[NC];
    float v = 0.f;
    #pragma unroll
    for (int c = 0; c < NC; ++c) { a[c] = 0.f; t[c] = 0.f; }
    for (int j = lane; j < SLOTS_PER_B; j += 32) {
        const float* p = g_part[w * SLOTS_PER_B + j];
        #pragma unroll
        for (int c = 0; c < NC; ++c) {
            a[c] += __ldcg(&p[c]);
            t[c] += __ldcg(&p[NC + c]);
        }
        v += __ldcg(&p[16]);
    }
    #pragma unroll
    for (int m = 16; m >= 1; m >>= 1) {
        #pragma unroll
        for (int c = 0; c < NC; ++c) {
            a[c] += __shfl_xor_sync(0xffffffffu, a[c], m);
            t[c] += __shfl_xor_sync(0xffffffffu, t[c], m);
        }
        v += __shfl_xor_sync(0xffffffffu, v, m);
    }
    if (lane == 0) {
        sh_ttv[w] = v;
        #pragma unroll
        for (int c = 0; c < NC; ++c) { sh_act[w][c] = a[c]; sh_tot[w][c] = t[c]; }
    }
    __syncthreads();

    if (threadIdx.x < NB) {
        const int bb = threadIdx.x;
        float tv = 0.f;
        #pragma unroll
        for (int i = 0; i < NB; ++i) tv += sh_ttv[i];
        float ah = 0.f, bh = 0.f;
        #pragma unroll
        for (int c = 0; c < NC; ++c) {
            const float aa = sh_act[bb][c];
            const float tt = sh_tot[bb][c];
            float e  = aa - __ldg(&count[bb * NC + c]);
            float ae = fabsf(e);
            ah += (ae <= 1.f) ? 0.5f * e * e : (ae - 0.5f);
            float eb  = tt - aa;
            float aeb = fabsf(eb);
            bh += (aeb <= 1.f) ? 0.5f * eb * eb : (aeb - 0.5f);
        }
        out[bb] = ah * (1.f / NC) + bh * (1.f / NC) + tv * 0.1f;
    }
}

extern "C" void kernel_launch(void* const* d_in, const int* in_sizes, int n_in,
                              void* d_out, int out_size) {
    const float* cam    = (const float*)d_in[0];
    const float* count  = (const float*)d_in[1];
    const int*   length = (const int*)d_in[2];
    float*       out    = (float*)d_out;

    dim3 grid(NBLK_S, KCH, NB);
    reduce_kernel<<<grid, BT>>>((const float4*)cam, length);
    final_kernel<<<1, 512>>>(count, out);
}

// round 5
// speedup vs baseline: 1.3523x; 1.1625x over previous
#include <cuda_runtime.h>

// Problem constants (fixed shapes from the reference setup)
#define NB   16      // batch
#define NT   128     // time
#define NHWC 25088   // 56*56*8 floats per frame
#define NS4  6272    // NHWC / 4 (float4 strips per frame)
#define NC   8       // channels
#define KCH  4       // time chunks
#define TC   (NT / KCH)             // 32 frames per chunk
#define BT   224                    // block threads; NS4 = 28 * 224 exactly
#define NW   (BT / 32)              // 7 warps
#define NBLK_S (NS4 / BT)           // 28 blocks over the spatial strip
#define SLOTS_PER_B (KCH * NBLK_S)  // 112
#define NBLKS  (NB * SLOTS_PER_B)   // 1792 total blocks
#define NFLD   17                   // 8 act + 8 tot + 1 ttv

// Scratch (no device allocation allowed -> __device__ globals).
// FIELD-MAJOR layout: g_part[field][slot] so the final kernel's lane-consecutive
// slot reads are perfectly coalesced (1 line per 32-lane LDG).
// Every block writes all its fields every launch => no init kernel needed.
__device__ float g_part[NFLD][NBLKS];

__global__ __launch_bounds__(BT) void reduce_kernel(const float4* __restrict__ x,
                                                    const int* __restrict__ length) {
    const int s4    = blockIdx.x * BT + threadIdx.x;   // always < NS4
    const int b     = blockIdx.z;
    const int chunk = blockIdx.y;
    const int len   = __ldg(&length[b]);
    const int t0    = chunk * TC;
    const float4* base = x + (size_t)b * NT * NS4 + s4;

    float ax = 0.f, ay = 0.f, az = 0.f, aw = 0.f;   // active sums (4 channels)
    float tx = 0.f, ty = 0.f, tz = 0.f, tw = 0.f;   // total sums
    float ttv = 0.f;
    float px = 0.f, py = 0.f, pz = 0.f, pw = 0.f;   // previous masked frame

    if (t0 > 0 && (t0 - 1) < len) {
        float4 p = __ldcs(&base[(size_t)(t0 - 1) * NS4]);
        px = p.x; py = p.y; pz = p.z; pw = p.w;
    }
    #pragma unroll 8
    for (int t = t0; t < t0 + TC; ++t) {
        float4 v = __ldcs(&base[(size_t)t * NS4]);
        tx += v.x; ty += v.y; tz += v.z; tw += v.w;
        float cx, cy, cz, cw;
        if (t < len) {
            cx = v.x; cy = v.y; cz = v.z; cw = v.w;
            ax += v.x; ay += v.y; az += v.z; aw += v.w;
        } else {
            cx = 0.f; cy = 0.f; cz = 0.f; cw = 0.f;
        }
        if (t > 0) {   // skip only the global t=0 (chunk 0, first iter)
            ttv += fabsf(cx - px) + fabsf(cy - py) + fabsf(cz - pz) + fabsf(cw - pw);
        }
        px = cx; py = cy; pz = cz; pw = cw;
    }

    // --- block reduction ---
    #pragma unroll
    for (int m = 16; m >= 1; m >>= 1)
        ttv += __shfl_xor_sync(0xffffffffu, ttv, m);
    // Parity-preserving reduce: even lanes hold channels 0-3, odd lanes 4-7
    #pragma unroll
    for (int m = 2; m <= 16; m <<= 1) {
        ax += __shfl_xor_sync(0xffffffffu, ax, m);
        ay += __shfl_xor_sync(0xffffffffu, ay, m);
        az += __shfl_xor_sync(0xffffffffu, az, m);
        aw += __shfl_xor_sync(0xffffffffu, aw, m);
        tx += __shfl_xor_sync(0xffffffffu, tx, m);
        ty += __shfl_xor_sync(0xffffffffu, ty, m);
        tz += __shfl_xor_sync(0xffffffffu, tz, m);
        tw += __shfl_xor_sync(0xffffffffu, tw, m);
    }

    __shared__ float sh_a[NW][NC];
    __shared__ float sh_t[NW][NC];
    __shared__ float sh_v[NW];
    const int w = threadIdx.x >> 5, lane = threadIdx.x & 31;
    if (lane == 0) {
        sh_a[w][0] = ax; sh_a[w][1] = ay; sh_a[w][2] = az; sh_a[w][3] = aw;
        sh_t[w][0] = tx; sh_t[w][1] = ty; sh_t[w][2] = tz; sh_t[w][3] = tw;
        sh_v[w] = ttv;
    } else if (lane == 1) {
        sh_a[w][4] = ax; sh_a[w][5] = ay; sh_a[w][6] = az; sh_a[w][7] = aw;
        sh_t[w][4] = tx; sh_t[w][5] = ty; sh_t[w][6] = tz; sh_t[w][7] = tw;
    }
    __syncthreads();

    const int slot = (b * KCH + chunk) * NBLK_S + blockIdx.x;
    if (threadIdx.x < NC) {
        const int c = threadIdx.x;
        float sa = 0.f, st = 0.f;
        #pragma unroll
        for (int w2 = 0; w2 < NW; ++w2) { sa += sh_a[w2][c]; st += sh_t[w2][c]; }
        g_part[c][slot]      = sa;
        g_part[NC + c][slot] = st;
    } else if (threadIdx.x == NC) {
        float s = 0.f;
        #pragma unroll
        for (int w2 = 0; w2 < NW; ++w2) s += sh_v[w2];
        g_part[16][slot] = s;
    }
}

__global__ __launch_bounds__(512) void final_kernel(const float* __restrict__ count,
                                                    float* __restrict__ out) {
    __shared__ float sh_fld[NB][NFLD];
    const int w = threadIdx.x >> 5, lane = threadIdx.x & 31;  // 16 warps, one per batch

    // Each warp reduces its batch's 112 slots for all 17 fields.
    // Loads are perfectly coalesced (consecutive lanes -> consecutive slots)
    // and all loads are independent (high MLP). 112 = 3*32 + 16: three full
    // strided loads plus one tail load predicated on lane < 16.
    float s[NFLD];
    #pragma unroll
    for (int f = 0; f < NFLD; ++f) {
        const float* p = &g_part[f][w * SLOTS_PER_B + lane];
        float acc = __ldcg(&p[0]) + __ldcg(&p[32]) + __ldcg(&p[64]);
        if (lane < 16) acc += __ldcg(&p[96]);
        s[f] = acc;
    }
    #pragma unroll
    for (int m = 16; m >= 1; m >>= 1) {
        #pragma unroll
        for (int f = 0; f < NFLD; ++f)
            s[f] += __shfl_xor_sync(0xffffffffu, s[f], m);
    }
    if (lane == 0) {
        #pragma unroll
        for (int f = 0; f < NFLD; ++f) sh_fld[w][f] = s[f];
    }
    __syncthreads();

    if (threadIdx.x < NB) {
        const int bb = threadIdx.x;
        float tv = 0.f;
        #pragma unroll
        for (int i = 0; i < NB; ++i) tv += sh_fld[i][16];
        float ah = 0.f, bh = 0.f;
        #pragma unroll
        for (int c = 0; c < NC; ++c) {
            const float aa = sh_fld[bb][c];
            const float tt = sh_fld[bb][NC + c];
            float e  = aa - __ldg(&count[bb * NC + c]);
            float ae = fabsf(e);
            ah += (ae <= 1.f) ? 0.5f * e * e : (ae - 0.5f);
            float eb  = tt - aa;
            float aeb = fabsf(eb);
            bh += (aeb <= 1.f) ? 0.5f * eb * eb : (aeb - 0.5f);
        }
        out[bb] = ah * (1.f / NC) + bh * (1.f / NC) + tv * 0.1f;
    }
}

extern "C" void kernel_launch(void* const* d_in, const int* in_sizes, int n_in,
                              void* d_out, int out_size) {
    const float* cam    = (const float*)d_in[0];
    const float* count  = (const float*)d_in[1];
    const int*   length = (const int*)d_in[2];
    float*       out    = (float*)d_out;

    dim3 grid(NBLK_S, KCH, NB);
    reduce_kernel<<<grid, BT>>>((const float4*)cam, length);
    final_kernel<<<1, 512>>>(count, out);
}

// round 6
// speedup vs baseline: 1.4820x; 1.0959x over previous
#include <cuda_runtime.h>

// Problem constants (fixed shapes from the reference setup)
#define NB   16      // batch
#define NT   128     // time
#define NHWC 25088   // 56*56*8 floats per frame
#define NS4  6272    // NHWC / 4 (float4 strips per frame)
#define NC   8       // channels
#define KCH  4       // time chunks
#define TC   (NT / KCH)             // 32 frames per chunk
#define BT   224                    // block threads; NS4 = 28 * 224 exactly
#define NW   (BT / 32)              // 7 warps
#define NBLK_S (NS4 / BT)           // 28 blocks over the spatial strip
#define SLOTS_PER_B (KCH * NBLK_S)  // 112
#define NBLKS  (NB * SLOTS_PER_B)   // 1792 total blocks
#define NFLD   17                   // 8 act + 8 tot + 1 ttv

// Scratch (no device allocation allowed -> __device__ globals).
// FIELD-MAJOR layout: g_part[field][slot] so the final kernel's lane-consecutive
// slot reads are perfectly coalesced (1 line per 32-lane LDG).
// Every block writes all its fields every launch => no init kernel needed.
__device__ float g_part[NFLD][NBLKS];

__global__ __launch_bounds__(BT) void reduce_kernel(const float4* __restrict__ x,
                                                    const int* __restrict__ length) {
    const int s4    = blockIdx.x * BT + threadIdx.x;   // always < NS4
    const int b     = blockIdx.z;
    const int chunk = blockIdx.y;
    const int len   = __ldg(&length[b]);
    const int t0    = chunk * TC;
    const float4* base = x + (size_t)b * NT * NS4 + s4;

    float ax = 0.f, ay = 0.f, az = 0.f, aw = 0.f;   // active sums (4 channels)
    float tx = 0.f, ty = 0.f, tz = 0.f, tw = 0.f;   // total sums
    float ttv = 0.f;
    float px = 0.f, py = 0.f, pz = 0.f, pw = 0.f;   // previous masked frame

    if (t0 > 0 && (t0 - 1) < len) {
        float4 p = __ldcs(&base[(size_t)(t0 - 1) * NS4]);
        px = p.x; py = p.y; pz = p.z; pw = p.w;
    }
    #pragma unroll 8
    for (int t = t0; t < t0 + TC; ++t) {
        float4 v = __ldcs(&base[(size_t)t * NS4]);
        tx += v.x; ty += v.y; tz += v.z; tw += v.w;
        float cx, cy, cz, cw;
        if (t < len) {
            cx = v.x; cy = v.y; cz = v.z; cw = v.w;
            ax += v.x; ay += v.y; az += v.z; aw += v.w;
        } else {
            cx = 0.f; cy = 0.f; cz = 0.f; cw = 0.f;
        }
        if (t > 0) {   // skip only the global t=0 (chunk 0, first iter)
            ttv += fabsf(cx - px) + fabsf(cy - py) + fabsf(cz - pz) + fabsf(cw - pw);
        }
        px = cx; py = cy; pz = cz; pw = cw;
    }

    // --- block reduction ---
    #pragma unroll
    for (int m = 16; m >= 1; m >>= 1)
        ttv += __shfl_xor_sync(0xffffffffu, ttv, m);
    // Parity-preserving reduce: even lanes hold channels 0-3, odd lanes 4-7
    #pragma unroll
    for (int m = 2; m <= 16; m <<= 1) {
        ax += __shfl_xor_sync(0xffffffffu, ax, m);
        ay += __shfl_xor_sync(0xffffffffu, ay, m);
        az += __shfl_xor_sync(0xffffffffu, az, m);
        aw += __shfl_xor_sync(0xffffffffu, aw, m);
        tx += __shfl_xor_sync(0xffffffffu, tx, m);
        ty += __shfl_xor_sync(0xffffffffu, ty, m);
        tz += __shfl_xor_sync(0xffffffffu, tz, m);
        tw += __shfl_xor_sync(0xffffffffu, tw, m);
    }

    __shared__ float sh_a[NW][NC];
    __shared__ float sh_t[NW][NC];
    __shared__ float sh_v[NW];
    const int w = threadIdx.x >> 5, lane = threadIdx.x & 31;
    if (lane == 0) {
        sh_a[w][0] = ax; sh_a[w][1] = ay; sh_a[w][2] = az; sh_a[w][3] = aw;
        sh_t[w][0] = tx; sh_t[w][1] = ty; sh_t[w][2] = tz; sh_t[w][3] = tw;
        sh_v[w] = ttv;
    } else if (lane == 1) {
        sh_a[w][4] = ax; sh_a[w][5] = ay; sh_a[w][6] = az; sh_a[w][7] = aw;
        sh_t[w][4] = tx; sh_t[w][5] = ty; sh_t[w][6] = tz; sh_t[w][7] = tw;
    }
    __syncthreads();

    const int slot = (b * KCH + chunk) * NBLK_S + blockIdx.x;
    if (threadIdx.x < NC) {
        const int c = threadIdx.x;
        float sa = 0.f, st = 0.f;
        #pragma unroll
        for (int w2 = 0; w2 < NW; ++w2) { sa += sh_a[w2][c]; st += sh_t[w2][c]; }
        g_part[c][slot]      = sa;
        g_part[NC + c][slot] = st;
    } else if (threadIdx.x == NC) {
        float s = 0.f;
        #pragma unroll
        for (int w2 = 0; w2 < NW; ++w2) s += sh_v[w2];
        g_part[16][slot] = s;
    }

    // All partial stores for this block are done; release them to the
    // programmatically-dependent final kernel.
    __syncthreads();
    cudaTriggerProgrammaticLaunchCompletion();
}

// One block per batch element; no inter-block dependency.
__global__ __launch_bounds__(256) void final_kernel(const float* __restrict__ count,
                                                    float* __restrict__ out) {
    const int b    = blockIdx.x;
    const int w    = threadIdx.x >> 5;     // 8 warps
    const int lane = threadIdx.x & 31;

    __shared__ float sh_fld[16];   // 8 act + 8 tot for this batch
    __shared__ float sh_ttv[8];    // per-warp ttv partials

    // Wait for the upstream grid's g_part writes to be visible.
    cudaGridDependencySynchronize();

    // Fields: warp w reduces fields 2w and 2w+1 over this batch's 112 slots.
    {
        const int base = b * SLOTS_PER_B + lane;
        #pragma unroll
        for (int k = 0; k < 2; ++k) {
            const int f = 2 * w + k;
            const float* p = &g_part[f][base];
            float acc = __ldcg(&p[0]) + __ldcg(&p[32]) + __ldcg(&p[64]);
            if (lane < 16) acc += __ldcg(&p[96]);
            #pragma unroll
            for (int m = 16; m >= 1; m >>= 1)
                acc += __shfl_xor_sync(0xffffffffu, acc, m);
            if (lane == 0) sh_fld[f] = acc;
        }
    }

    // TTV: every block sums all 1792 ttv partials (same value for all b).
    {
        float v = 0.f;
        #pragma unroll
        for (int k = 0; k < NBLKS / 256; ++k)
            v += __ldcg(&g_part[16][k * 256 + threadIdx.x]);
        #pragma unroll
        for (int m = 16; m >= 1; m >>= 1)
            v += __shfl_xor_sync(0xffffffffu, v, m);
        if (lane == 0) sh_ttv[w] = v;
    }
    __syncthreads();

    if (threadIdx.x == 0) {
        float tv = 0.f;
        #pragma unroll
        for (int i = 0; i < 8; ++i) tv += sh_ttv[i];
        float ah = 0.f, bh = 0.f;
        #pragma unroll
        for (int c = 0; c < NC; ++c) {
            const float aa = sh_fld[c];
            const float tt = sh_fld[NC + c];
            float e  = aa - __ldg(&count[b * NC + c]);
            float ae = fabsf(e);
            ah += (ae <= 1.f) ? 0.5f * e * e : (ae - 0.5f);
            float eb  = tt - aa;
            float aeb = fabsf(eb);
            bh += (aeb <= 1.f) ? 0.5f * eb * eb : (aeb - 0.5f);
        }
        out[b] = ah * (1.f / NC) + bh * (1.f / NC) + tv * 0.1f;
    }
}

extern "C" void kernel_launch(void* const* d_in, const int* in_sizes, int n_in,
                              void* d_out, int out_size) {
    const float* cam    = (const float*)d_in[0];
    const float* count  = (const float*)d_in[1];
    const int*   length = (const int*)d_in[2];
    float*       out    = (float*)d_out;

    dim3 grid(NBLK_S, KCH, NB);
    reduce_kernel<<<grid, BT>>>((const float4*)cam, length);

    // Programmatic dependent launch: final_kernel's launch/ramp overlaps the
    // reduce kernel's tail; cudaGridDependencySynchronize() inside guards the
    // g_part reads.
    cudaLaunchConfig_t cfg = {};
    cfg.gridDim  = dim3(NB, 1, 1);
    cfg.blockDim = dim3(256, 1, 1);
    cfg.stream   = 0;
    cudaLaunchAttribute attrs[1];
    attrs[0].id = cudaLaunchAttributeProgrammaticStreamSerialization;
    attrs[0].val.programmaticStreamSerializationAllowed = 1;
    cfg.attrs    = attrs;
    cfg.numAttrs = 1;
    cudaLaunchKernelEx(&cfg, final_kernel, count, out);
}